// round 1
// baseline (speedup 1.0000x reference)
#include <cuda_runtime.h>
#include <math.h>

// ---------------- problem constants ----------------
// x:      [512, 1, 28, 28]
// conv_w: [256, 1, 9, 9]   conv_b: [256]
// y:      [512, 256, 20, 20]
// prim_w: [256*? = 256 oc][256 ic][9][9], stride 2 -> p: [512, 256, 6, 6]
// u:      [512, 1152, 8]   (r = m*36 + oh*6 + ow, i = oc>>5, m = oc&31)
// route_w:[10, 1152, 8, 16]
// out:    [512, 10]

#define NB 512

// ---------------- scratch (device globals; no runtime alloc) ----------------
__device__ float g_y[(size_t)NB * 256 * 400];       // 210 MB
__device__ float g_u[(size_t)NB * 1152 * 8];        // 18.9 MB (p, squashed in place)
__device__ float g_logits[NB * 10];

// ======================================================================
// conv1: block = (oh, b), 256 threads = oc. Full conv_w in smem (83KB),
// one 9x28 input slab in smem. Each thread register-tiles all 20 ow.
// ======================================================================
__global__ void conv1_kernel(const float* __restrict__ x,
                             const float* __restrict__ w,
                             const float* __restrict__ bias) {
    extern __shared__ float sm1[];
    float* sw = sm1;            // 20736 floats
    float* sx = sm1 + 20736;    // 252 floats
    int oh = blockIdx.x, b = blockIdx.y, t = threadIdx.x;

    for (int i = t; i < 20736; i += 256) sw[i] = w[i];
    if (t < 252) sx[t] = x[(size_t)b * 784 + oh * 28 + t];
    __syncthreads();

    int oc = t;
    float acc[20];
    float bv = bias[oc];
#pragma unroll
    for (int i = 0; i < 20; i++) acc[i] = bv;

    const float* wp = sw + oc * 81;
#pragma unroll
    for (int kh = 0; kh < 9; kh++) {
        float rin[28];
#pragma unroll
        for (int j = 0; j < 28; j++) rin[j] = sx[kh * 28 + j];
#pragma unroll
        for (int kw = 0; kw < 9; kw++) {
            float wv = wp[kh * 9 + kw];
#pragma unroll
            for (int ow = 0; ow < 20; ow++) acc[ow] += wv * rin[kw + ow];
        }
    }
    float* yp = g_y + ((size_t)(b * 256 + oc)) * 400 + oh * 20;
#pragma unroll
    for (int ow = 0; ow < 20; ow++) yp[ow] = acc[ow];
}

// ======================================================================
// conv2 (primary caps): implicit GEMM.
// Block = 4 images x 64 oc. 576 threads = 16 oc-threads x 36 pix-threads.
// Thread register tile: 4 oc x 4 pixels (2x2 output quad).
// Loop over 256 input channels; per ic stage: w tile [81][64] + 4 input
// planes [20][20] in smem. Per tap: 1 LDS.128 + 4 LDS.32 + 16 FFMA.
// Writes directly in u layout [b][r][i] (transposed caps layout) + bias.
// ======================================================================
__global__ void __launch_bounds__(576, 2) conv2_kernel(
        const float* __restrict__ pw, const float* __restrict__ pb) {
    __shared__ float sw[81 * 64];     // [tap][oc]
    __shared__ float sy[4 * 400];     // [img][20][20]
    int ocb = blockIdx.x * 64;
    int b0  = blockIdx.y * 4;
    int t = threadIdx.x;

    int oc_thr = t & 15;          // 16 groups of 4 oc
    int pix_thr = t >> 4;         // 36: img(4) x quad(9)
    int img_l = pix_thr / 9;
    int quad  = pix_thr % 9;
    int qh = quad / 3, qw = quad % 3;

    float acc[4][4];
#pragma unroll
    for (int p = 0; p < 4; p++)
#pragma unroll
        for (int o = 0; o < 4; o++) acc[p][o] = 0.f;

    int lo = t / 9, lj = t % 9;   // weight loader: oc=lo, 9 contiguous taps
    const float* pin0 = sy + img_l * 400 + qh * 4 * 20 + qw * 4;

    for (int ic = 0; ic < 256; ic++) {
        __syncthreads();   // previous stage consumed
        {
            const float* wg = pw + ((size_t)(ocb + lo) * 256 + ic) * 81 + lj * 9;
#pragma unroll
            for (int q = 0; q < 9; q++) sw[(lj * 9 + q) * 64 + lo] = wg[q];
        }
        for (int i = t; i < 1600; i += 576) {
            int im = i / 400, off = i % 400;
            sy[i] = g_y[((size_t)(b0 + im) * 256 + ic) * 400 + off];
        }
        __syncthreads();

#pragma unroll
        for (int kh = 0; kh < 9; kh++) {
#pragma unroll
            for (int kw = 0; kw < 9; kw++) {
                float4 w4 = *(const float4*)&sw[(kh * 9 + kw) * 64 + oc_thr * 4];
                float i00 = pin0[kh * 20 + kw];
                float i01 = pin0[kh * 20 + kw + 2];
                float i10 = pin0[(kh + 2) * 20 + kw];
                float i11 = pin0[(kh + 2) * 20 + kw + 2];
                acc[0][0] += i00 * w4.x; acc[0][1] += i00 * w4.y;
                acc[0][2] += i00 * w4.z; acc[0][3] += i00 * w4.w;
                acc[1][0] += i01 * w4.x; acc[1][1] += i01 * w4.y;
                acc[1][2] += i01 * w4.z; acc[1][3] += i01 * w4.w;
                acc[2][0] += i10 * w4.x; acc[2][1] += i10 * w4.y;
                acc[2][2] += i10 * w4.z; acc[2][3] += i10 * w4.w;
                acc[3][0] += i11 * w4.x; acc[3][1] += i11 * w4.y;
                acc[3][2] += i11 * w4.z; acc[3][3] += i11 * w4.w;
            }
        }
    }

#pragma unroll
    for (int oo = 0; oo < 4; oo++) {
        int oc = ocb + oc_thr * 4 + oo;
        float bv = pb[oc];
        int i8 = oc >> 5, m = oc & 31;
#pragma unroll
        for (int dh = 0; dh < 2; dh++)
#pragma unroll
            for (int dw = 0; dw < 2; dw++) {
                int oh = 2 * qh + dh, ow = 2 * qw + dw;
                int r = m * 36 + oh * 6 + ow;
                g_u[((size_t)(b0 + img_l) * 1152 + r) * 8 + i8] =
                    acc[dh * 2 + dw][oo] + bv;
            }
    }
}

// ======================================================================
// squash u over the 8-dim capsule axis (in place on g_u).
// ======================================================================
__global__ void squash_kernel() {
    int idx = blockIdx.x * blockDim.x + threadIdx.x;
    if (idx >= NB * 1152) return;
    float* p = g_u + (size_t)idx * 8;
    float4 a = *(float4*)p, b = *(float4*)(p + 4);
    float sn = a.x*a.x + a.y*a.y + a.z*a.z + a.w*a.w
             + b.x*b.x + b.y*b.y + b.z*b.z + b.w*b.w;
    float sc = sqrtf(sn) / (1.f + sn);
    a.x *= sc; a.y *= sc; a.z *= sc; a.w *= sc;
    b.x *= sc; b.y *= sc; b.z *= sc; b.w *= sc;
    *(float4*)p = a; *(float4*)(p + 4) = b;
}

// ======================================================================
// Fused priors + 3 dynamic-routing iterations. Block = (c, b).
// priors[1152][16] (73.7KB) + u[1152][8] (36.9KB) + blog (4.6KB) in smem.
// route_w[c] (590KB) streamed from L2 once per block.
// ======================================================================
__global__ void route_kernel(const float* __restrict__ rw) {
    extern __shared__ float sm2[];
    float* spri  = sm2;               // 18432
    float* su    = sm2 + 18432;       // 9216
    float* sblog = su + 9216;         // 1152
    float* sred  = sblog + 1152;      // 128
    float* sv    = sred + 128;        // 16
    float* sscr  = sv + 16;           // 24
    int c = blockIdx.x, b = blockIdx.y, t = threadIdx.x;
    int lane = t & 31, warp = t >> 5;

    {
        const float4* ug = (const float4*)(g_u + (size_t)b * 9216);
        float4* su4 = (float4*)su;
        for (int i = t; i < 2304; i += 256) su4[i] = ug[i];
        for (int r = t; r < 1152; r += 256) sblog[r] = 0.f;
    }
    __syncthreads();

    // priors[r][o] = sum_i u[r][i] * route_w[c][r][i][o]
    {
        int o4 = (t & 3) * 4, rb = t >> 2;
        for (int j = 0; j < 18; j++) {
            int r = rb + 64 * j;
            const float* wr = rw + ((size_t)c * 1152 + r) * 128 + o4;
            const float* ur = su + r * 8;
            float ax = 0.f, ay = 0.f, az = 0.f, aw = 0.f;
#pragma unroll
            for (int i = 0; i < 8; i++) {
                float uv = ur[i];
                float4 w = *(const float4*)(wr + i * 16);
                ax += uv * w.x; ay += uv * w.y; az += uv * w.z; aw += uv * w.w;
            }
            float4 o; o.x = ax; o.y = ay; o.z = az; o.w = aw;
            *(float4*)(spri + r * 16 + o4) = o;
        }
    }
    __syncthreads();

    float snv = 0.f;
    for (int iter = 0; iter < 3; iter++) {
        // block max of blog
        float lm = -1e30f;
        for (int r = t; r < 1152; r += 256) lm = fmaxf(lm, sblog[r]);
#pragma unroll
        for (int off = 16; off; off >>= 1)
            lm = fmaxf(lm, __shfl_xor_sync(0xffffffffu, lm, off));
        if (lane == 0) sscr[warp] = lm;
        __syncthreads();
        float bmax = sscr[0];
#pragma unroll
        for (int wn = 1; wn < 8; wn++) bmax = fmaxf(bmax, sscr[wn]);
        // block sum of exp
        float ls = 0.f;
        for (int r = t; r < 1152; r += 256) ls += expf(sblog[r] - bmax);
#pragma unroll
        for (int off = 16; off; off >>= 1)
            ls += __shfl_xor_sync(0xffffffffu, ls, off);
        if (lane == 0) sscr[8 + warp] = ls;
        __syncthreads();
        float bsum = 0.f;
#pragma unroll
        for (int wn = 0; wn < 8; wn++) bsum += sscr[8 + wn];
        float inv = 1.f / bsum;

        // s[o] = sum_r priors[r][o] * softmax(blog)[r]
        float sa[16];
#pragma unroll
        for (int o = 0; o < 16; o++) sa[o] = 0.f;
        for (int r = t; r < 1152; r += 256) {
            float pr = expf(sblog[r] - bmax) * inv;
            const float* pp = spri + r * 16;
#pragma unroll
            for (int o = 0; o < 16; o++) sa[o] += pp[o] * pr;
        }
#pragma unroll
        for (int o = 0; o < 16; o++) {
#pragma unroll
            for (int off = 16; off; off >>= 1)
                sa[o] += __shfl_xor_sync(0xffffffffu, sa[o], off);
        }
        if (lane == 0) {
#pragma unroll
            for (int o = 0; o < 16; o++) sred[warp * 16 + o] = sa[o];
        }
        __syncthreads();
        if (t < 32) {
            float sval = 0.f;
            if (t < 16) {
#pragma unroll
                for (int wn = 0; wn < 8; wn++) sval += sred[wn * 16 + t];
            }
            float sn = sval * sval;
#pragma unroll
            for (int off = 16; off; off >>= 1)
                sn += __shfl_xor_sync(0xffffffffu, sn, off);
            float sc = sqrtf(sn) / (1.f + sn);
            if (t < 16) sv[t] = sval * sc;
            if (t == 0) sscr[16] = sn;
        }
        __syncthreads();
        snv = sscr[16];

        if (iter < 2) {
            for (int r = t; r < 1152; r += 256) {
                const float* pp = spri + r * 16;
                float d = 0.f;
#pragma unroll
                for (int o = 0; o < 16; o++) d += pp[o] * sv[o];
                sblog[r] += d;
            }
            __syncthreads();
        }
    }
    // logits = ||v|| = sn/(1+sn)
    if (t == 0) g_logits[b * 10 + c] = snv / (1.f + snv);
}

// ======================================================================
// Final class softmax over 10 logits per sample.
// ======================================================================
__global__ void softmax_kernel(float* __restrict__ out) {
    int b = blockIdx.x * blockDim.x + threadIdx.x;
    if (b >= NB) return;
    float l[10];
#pragma unroll
    for (int i = 0; i < 10; i++) l[i] = g_logits[b * 10 + i];
    float m = l[0];
#pragma unroll
    for (int i = 1; i < 10; i++) m = fmaxf(m, l[i]);
    float s = 0.f;
#pragma unroll
    for (int i = 0; i < 10; i++) { l[i] = expf(l[i] - m); s += l[i]; }
    float inv = 1.f / s;
#pragma unroll
    for (int i = 0; i < 10; i++) out[b * 10 + i] = l[i] * inv;
}

// ======================================================================
extern "C" void kernel_launch(void* const* d_in, const int* in_sizes, int n_in,
                              void* d_out, int out_size) {
    const float* x  = (const float*)d_in[0];
    const float* cw = (const float*)d_in[1];
    const float* cb = (const float*)d_in[2];
    const float* pw = (const float*)d_in[3];
    const float* pb = (const float*)d_in[4];
    const float* rw = (const float*)d_in[5];
    float* out = (float*)d_out;

    const int c1_smem = (20736 + 252) * 4;     // 83,952 B
    const int rt_smem = (18432 + 9216 + 1152 + 128 + 16 + 24) * 4;  // 115,872 B
    cudaFuncSetAttribute(conv1_kernel,
        cudaFuncAttributeMaxDynamicSharedMemorySize, c1_smem);
    cudaFuncSetAttribute(route_kernel,
        cudaFuncAttributeMaxDynamicSharedMemorySize, rt_smem);

    conv1_kernel<<<dim3(20, NB), 256, c1_smem>>>(x, cw, cb);
    conv2_kernel<<<dim3(4, NB / 4), 576>>>(pw, pb);
    squash_kernel<<<(NB * 1152 + 255) / 256, 256>>>();
    route_kernel<<<dim3(10, NB), 256, rt_smem>>>(rw);
    softmax_kernel<<<(NB + 255) / 256, 256>>>(out);
}

// round 3
// speedup vs baseline: 1.8098x; 1.8098x over previous
#include <cuda_runtime.h>
#include <math.h>
#include <cstdint>

// ---------------- problem constants ----------------
// x:      [512, 1, 28, 28]
// conv_w: [256, 1, 9, 9]   conv_b: [256]
// y:      [512, 256, 20, 20]
// prim_w: [256 oc][256 ic][9][9], stride 2 -> p: [512, 256, 6, 6]
// u:      [512, 1152, 8]   (r = m*36 + oh*6 + ow, i = oc>>5, m = oc&31)
// route_w:[10, 1152, 8, 16]
// out:    [512, 10]

#define NB 512

// ---------------- scratch ----------------
__device__ float g_y[(size_t)NB * 256 * 400];        // 210 MB
__device__ float g_u[(size_t)NB * 1152 * 8];         // 18.9 MB
__device__ float g_wtf[(size_t)2 * 256 * 128 * 100]; // 26.2 MB  [half][ic][ocl][k100] tf32
__device__ float g_logits[NB * 10];

__device__ __forceinline__ float to_tf32(float v) {
    uint32_t r;
    asm("cvt.rna.tf32.f32 %0, %1;" : "=r"(r) : "f"(v));
    return __uint_as_float(r);
}

// ======================================================================
// weight prep: prim_w -> [half][ic][ocl][100] tf32 (taps 81..99 zero)
// ======================================================================
__global__ void prep_w_kernel(const float* __restrict__ pw) {
    size_t idx = (size_t)blockIdx.x * 256 + threadIdx.x;
    if (idx >= (size_t)2 * 256 * 128 * 100) return;
    int kk = (int)(idx % 100);
    size_t r = idx / 100;
    int ocl = (int)(r % 128);
    size_t r2 = r / 128;
    int ic = (int)(r2 % 256);
    int half = (int)(r2 / 256);
    float v = 0.f;
    if (kk < 81)
        v = pw[((size_t)(half * 128 + ocl)) * 20736 + ic * 81 + kk];
    g_wtf[idx] = to_tf32(v);
}

// ======================================================================
// conv1: block = (oh, b), 256 threads = oc
// ======================================================================
__global__ void conv1_kernel(const float* __restrict__ x,
                             const float* __restrict__ w,
                             const float* __restrict__ bias) {
    extern __shared__ float sm1[];
    float* sw = sm1;
    float* sx = sm1 + 20736;
    int oh = blockIdx.x, b = blockIdx.y, t = threadIdx.x;

    for (int i = t; i < 20736; i += 256) sw[i] = w[i];
    if (t < 252) sx[t] = x[(size_t)b * 784 + oh * 28 + t];
    __syncthreads();

    int oc = t;
    float acc[20];
    float bv = bias[oc];
#pragma unroll
    for (int i = 0; i < 20; i++) acc[i] = bv;

    const float* wp = sw + oc * 81;
#pragma unroll
    for (int kh = 0; kh < 9; kh++) {
        float rin[28];
#pragma unroll
        for (int j = 0; j < 28; j++) rin[j] = sx[kh * 28 + j];
#pragma unroll
        for (int kw = 0; kw < 9; kw++) {
            float wv = wp[kh * 9 + kw];
#pragma unroll
            for (int ow = 0; ow < 20; ow++) acc[ow] += wv * rin[kw + ow];
        }
    }
    float* yp = g_y + ((size_t)(b * 256 + oc)) * 400 + oh * 20;
#pragma unroll
    for (int ow = 0; ow < 20; ow++) yp[ow] = acc[ow];
}

// ======================================================================
// conv2 via mma.sync tf32 m16n8k8.
// Block: 128 oc x 72 px (2 images). 256 thr = warps 4(M) x 2(N).
// Warp tile 32 oc x 40 px (px 72..79 zero pad). K = 256 ic x 96 (81 real).
// smem: A[128][100] + B[80][100] + y[2][400] = 86.4 KB -> 2 CTA/SM.
// ======================================================================
#define C2_SMEM ((12800 + 8000 + 800) * 4)

__global__ void __launch_bounds__(256, 2) conv2_mma_kernel(
        const float* __restrict__ pb) {
    extern __shared__ float sm[];
    float* aSm = sm;             // 12800
    float* bSm = sm + 12800;     // 8000
    float* ySm = sm + 20800;     // 800

    int t = threadIdx.x, lane = t & 31, wid = t >> 5;
    int gid = lane >> 2, tig = lane & 3;
    int wm = wid >> 1, wn = wid & 1;
    int half = blockIdx.x;
    int b0 = blockIdx.y * 2;

    // zero B once (pad rows 72..79 and taps 81..99 stay zero forever)
    for (int i = t; i < 8000; i += 256) bSm[i] = 0.f;

    // precompute B-gather geometry (ic-invariant)
    int gn = -1, ybase = 0, bdst = 0;
    if (t < 240) {
        int n = t % 80, kg = t / 80;   // kg: kh group 0..2
        if (n < 72) {
            int img = n >= 36;
            int pix = n - 36 * img;
            int oh = pix / 6, ow = pix - oh * 6;
            gn = n;
            ybase = img * 400 + (2 * oh + kg * 3) * 20 + 2 * ow;
            bdst = n * 100 + kg * 27;
        }
    }

    float acc[2][5][4];
#pragma unroll
    for (int mt = 0; mt < 2; mt++)
#pragma unroll
        for (int j = 0; j < 5; j++)
#pragma unroll
            for (int k = 0; k < 4; k++) acc[mt][j][k] = 0.f;

    const float* wsrc = g_wtf + (size_t)half * 256 * 12800;

    for (int ic = 0; ic < 256; ic++) {
        __syncthreads();   // previous mma phase / B-zero done
        // y planes (2 images)
        for (int i = t; i < 800; i += 256) {
            int im = i >= 400;
            ySm[i] = g_y[((size_t)(b0 + im) * 256 + ic) * 400 + (i - im * 400)];
        }
        // A copy (coalesced, already tf32)
        {
            const float4* as = (const float4*)(wsrc + (size_t)ic * 12800);
            float4* ad = (float4*)aSm;
            for (int i = t; i < 3200; i += 256) ad[i] = as[i];
        }
        __syncthreads();   // y ready
        if (gn >= 0) {
#pragma unroll
            for (int i = 0; i < 27; i++) {
                int kh = i / 9, kw = i % 9;   // compile-time
                bSm[bdst + i] = to_tf32(ySm[ybase + kh * 20 + kw]);
            }
        }
        __syncthreads();   // A,B ready

#pragma unroll
        for (int ks = 0; ks < 12; ks++) {
            int kc = ks * 8 + tig;
            uint32_t a[2][4];
#pragma unroll
            for (int mt = 0; mt < 2; mt++) {
                const float* ap = aSm + (wm * 32 + mt * 16 + gid) * 100 + kc;
                a[mt][0] = __float_as_uint(ap[0]);
                a[mt][1] = __float_as_uint(ap[800]);
                a[mt][2] = __float_as_uint(ap[4]);
                a[mt][3] = __float_as_uint(ap[804]);
            }
#pragma unroll
            for (int j = 0; j < 5; j++) {
                const float* bp = bSm + (wn * 40 + j * 8 + gid) * 100 + kc;
                uint32_t br0 = __float_as_uint(bp[0]);
                uint32_t br1 = __float_as_uint(bp[4]);
#pragma unroll
                for (int mt = 0; mt < 2; mt++) {
                    asm volatile(
                        "mma.sync.aligned.m16n8k8.row.col.f32.tf32.tf32.f32 "
                        "{%0,%1,%2,%3},{%4,%5,%6,%7},{%8,%9},{%0,%1,%2,%3};"
                        : "+f"(acc[mt][j][0]), "+f"(acc[mt][j][1]),
                          "+f"(acc[mt][j][2]), "+f"(acc[mt][j][3])
                        : "r"(a[mt][0]), "r"(a[mt][1]), "r"(a[mt][2]),
                          "r"(a[mt][3]), "r"(br0), "r"(br1));
                }
            }
        }
    }

    // epilogue: D[oc][n] -> g_u[b][r][i] + bias
    int ocb = half * 128;
#pragma unroll
    for (int mt = 0; mt < 2; mt++) {
        int row0 = wm * 32 + mt * 16 + gid;
#pragma unroll
        for (int h2 = 0; h2 < 2; h2++) {
            int oc = ocb + row0 + h2 * 8;
            float bv = pb[oc];
            int i8 = oc >> 5, m = oc & 31;
#pragma unroll
            for (int j = 0; j < 5; j++) {
#pragma unroll
                for (int cc = 0; cc < 2; cc++) {
                    int n = wn * 40 + j * 8 + 2 * tig + cc;
                    if (n < 72) {
                        int img = n >= 36;
                        int pix = n - 36 * img;
                        g_u[((size_t)(b0 + img)) * 9216 + (m * 36 + pix) * 8 + i8] =
                            acc[mt][j][h2 * 2 + cc] + bv;
                    }
                }
            }
        }
    }
}

// ======================================================================
// squash u over the 8-dim capsule axis (in place)
// ======================================================================
__global__ void squash_kernel() {
    int idx = blockIdx.x * blockDim.x + threadIdx.x;
    if (idx >= NB * 1152) return;
    float* p = g_u + (size_t)idx * 8;
    float4 a = *(float4*)p, b = *(float4*)(p + 4);
    float sn = a.x*a.x + a.y*a.y + a.z*a.z + a.w*a.w
             + b.x*b.x + b.y*b.y + b.z*b.z + b.w*b.w;
    float sc = sqrtf(sn) / (1.f + sn);
    a.x *= sc; a.y *= sc; a.z *= sc; a.w *= sc;
    b.x *= sc; b.y *= sc; b.z *= sc; b.w *= sc;
    *(float4*)p = a; *(float4*)(p + 4) = b;
}

// ======================================================================
// Fused priors + 3 routing iterations. Block = (c, b), 512 threads.
// ======================================================================
__global__ void route_kernel(const float* __restrict__ rw) {
    extern __shared__ float sm2[];
    float* spri  = sm2;               // 18432
    float* su    = sm2 + 18432;       // 9216
    float* sblog = su + 9216;         // 1152
    float* sred  = sblog + 1152;      // 256
    float* sv    = sred + 256;        // 16
    float* sscr  = sv + 16;           // 40
    int c = blockIdx.x, b = blockIdx.y, t = threadIdx.x;
    int lane = t & 31, warp = t >> 5;   // 16 warps

    {
        const float4* ug = (const float4*)(g_u + (size_t)b * 9216);
        float4* su4 = (float4*)su;
        for (int i = t; i < 2304; i += 512) su4[i] = ug[i];
        for (int r = t; r < 1152; r += 512) sblog[r] = 0.f;
    }
    __syncthreads();

    // priors[r][o] = sum_i u[r][i] * route_w[c][r][i][o]
    {
        int o4 = (t & 3) * 4, rb = t >> 2;   // rb 0..127
        for (int j = 0; j < 9; j++) {
            int r = rb + 128 * j;
            const float* wr = rw + ((size_t)c * 1152 + r) * 128 + o4;
            const float* ur = su + r * 8;
            float ax = 0.f, ay = 0.f, az = 0.f, aw = 0.f;
#pragma unroll
            for (int i = 0; i < 8; i++) {
                float uv = ur[i];
                float4 w = *(const float4*)(wr + i * 16);
                ax += uv * w.x; ay += uv * w.y; az += uv * w.z; aw += uv * w.w;
            }
            float4 o; o.x = ax; o.y = ay; o.z = az; o.w = aw;
            *(float4*)(spri + r * 16 + o4) = o;
        }
    }
    __syncthreads();

    float snv = 0.f;
    for (int iter = 0; iter < 3; iter++) {
        float lm = -1e30f;
        for (int r = t; r < 1152; r += 512) lm = fmaxf(lm, sblog[r]);
#pragma unroll
        for (int off = 16; off; off >>= 1)
            lm = fmaxf(lm, __shfl_xor_sync(0xffffffffu, lm, off));
        if (lane == 0) sscr[warp] = lm;
        __syncthreads();
        float bmax = sscr[0];
#pragma unroll
        for (int wn = 1; wn < 16; wn++) bmax = fmaxf(bmax, sscr[wn]);
        float ls = 0.f;
        for (int r = t; r < 1152; r += 512) ls += expf(sblog[r] - bmax);
#pragma unroll
        for (int off = 16; off; off >>= 1)
            ls += __shfl_xor_sync(0xffffffffu, ls, off);
        if (lane == 0) sscr[16 + warp] = ls;
        __syncthreads();
        float bsum = 0.f;
#pragma unroll
        for (int wn = 0; wn < 16; wn++) bsum += sscr[16 + wn];
        float inv = 1.f / bsum;

        float sa[16];
#pragma unroll
        for (int o = 0; o < 16; o++) sa[o] = 0.f;
        for (int r = t; r < 1152; r += 512) {
            float pr = expf(sblog[r] - bmax) * inv;
            const float* pp = spri + r * 16;
#pragma unroll
            for (int o = 0; o < 16; o++) sa[o] += pp[o] * pr;
        }
#pragma unroll
        for (int o = 0; o < 16; o++) {
#pragma unroll
            for (int off = 16; off; off >>= 1)
                sa[o] += __shfl_xor_sync(0xffffffffu, sa[o], off);
        }
        if (lane == 0) {
#pragma unroll
            for (int o = 0; o < 16; o++) sred[warp * 16 + o] = sa[o];
        }
        __syncthreads();
        if (t < 32) {
            float sval = 0.f;
            if (t < 16) {
#pragma unroll
                for (int wn = 0; wn < 16; wn++) sval += sred[wn * 16 + t];
            }
            float sn = sval * sval;
#pragma unroll
            for (int off = 16; off; off >>= 1)
                sn += __shfl_xor_sync(0xffffffffu, sn, off);
            float sc = sqrtf(sn) / (1.f + sn);
            if (t < 16) sv[t] = sval * sc;
            if (t == 0) sscr[32] = sn;
        }
        __syncthreads();
        snv = sscr[32];

        if (iter < 2) {
            for (int r = t; r < 1152; r += 512) {
                const float* pp = spri + r * 16;
                float d = 0.f;
#pragma unroll
                for (int o = 0; o < 16; o++) d += pp[o] * sv[o];
                sblog[r] += d;
            }
            __syncthreads();
        }
    }
    if (t == 0) g_logits[b * 10 + c] = snv / (1.f + snv);
}

// ======================================================================
__global__ void softmax_kernel(float* __restrict__ out) {
    int b = blockIdx.x * blockDim.x + threadIdx.x;
    if (b >= NB) return;
    float l[10];
#pragma unroll
    for (int i = 0; i < 10; i++) l[i] = g_logits[b * 10 + i];
    float m = l[0];
#pragma unroll
    for (int i = 1; i < 10; i++) m = fmaxf(m, l[i]);
    float s = 0.f;
#pragma unroll
    for (int i = 0; i < 10; i++) { l[i] = expf(l[i] - m); s += l[i]; }
    float inv = 1.f / s;
#pragma unroll
    for (int i = 0; i < 10; i++) out[b * 10 + i] = l[i] * inv;
}

// ======================================================================
extern "C" void kernel_launch(void* const* d_in, const int* in_sizes, int n_in,
                              void* d_out, int out_size) {
    const float* x  = (const float*)d_in[0];
    const float* cw = (const float*)d_in[1];
    const float* cb = (const float*)d_in[2];
    const float* pw = (const float*)d_in[3];
    const float* pb = (const float*)d_in[4];
    const float* rw = (const float*)d_in[5];
    float* out = (float*)d_out;

    const int c1_smem = (20736 + 252) * 4;
    const int rt_smem = (18432 + 9216 + 1152 + 256 + 16 + 40) * 4;
    cudaFuncSetAttribute(conv1_kernel,
        cudaFuncAttributeMaxDynamicSharedMemorySize, c1_smem);
    cudaFuncSetAttribute(conv2_mma_kernel,
        cudaFuncAttributeMaxDynamicSharedMemorySize, C2_SMEM);
    cudaFuncSetAttribute(route_kernel,
        cudaFuncAttributeMaxDynamicSharedMemorySize, rt_smem);

    prep_w_kernel<<<(2 * 256 * 128 * 100 + 255) / 256, 256>>>(pw);
    conv1_kernel<<<dim3(20, NB), 256, c1_smem>>>(x, cw, cb);
    conv2_mma_kernel<<<dim3(2, NB / 2), 256, C2_SMEM>>>(pb);
    squash_kernel<<<(NB * 1152 + 255) / 256, 256>>>();
    route_kernel<<<dim3(10, NB), 512, rt_smem>>>(rw);
    softmax_kernel<<<(NB + 255) / 256, 256>>>(out);
}